// round 8
// baseline (speedup 1.0000x reference)
#include <cuda_runtime.h>
#include <cstdint>

// out = (x @ Wv.T + bv) @ Wo.T + bo   (softmax over singleton axis == 1)
// R7: zero-smem, zero-barrier kernel. B fragments come straight from a
// pre-permuted, lane-contiguous tf32 weight image in GMEM (L1/L2-resident,
// perfectly coalesced LDG.128). x comes in via direct coalesced LDG.128 with
// the k-permutation baked into the weight image. Stage-1 accumulators feed
// stage-2 A-fragments in registers. Warps free-run: no syncthreads anywhere.

#define DIM      768
#define HH       64
#define TILE_M   128
#define NTHREADS 256                      // 8 warps, m16 rows each
#define NCH1     12
#define NCH      24
// W image: [c][nb][p] -> contiguous 512B block of lane-ordered uint4
#define WFRAG_WORDS (NCH * 8 * 4 * 32 * 4)   // 98304 words = 384 KB

__device__ uint32_t g_Wfrag[WFRAG_WORDS];

__device__ __forceinline__ uint32_t f2tf32(float f) {
    uint32_t r;
    asm("cvt.rna.tf32.f32 %0, %1;" : "=r"(r) : "f"(f));
    return r;
}

__device__ __forceinline__ void mma8(float d[4], const uint32_t a[4], uint32_t b0, uint32_t b1) {
    asm volatile(
        "mma.sync.aligned.m16n8k8.row.col.f32.tf32.tf32.f32 "
        "{%0,%1,%2,%3}, {%4,%5,%6,%7}, {%8,%9}, {%0,%1,%2,%3};\n"
        : "+f"(d[0]), "+f"(d[1]), "+f"(d[2]), "+f"(d[3])
        : "r"(a[0]), "r"(a[1]), "r"(a[2]), "r"(a[3]), "r"(b0), "r"(b1));
}

// Prologue: permute Wv/Wo into lane-contiguous fragment order, tf32.
// out word idx = (((c*8+nb)*4+p)*32+lane)*4 + q      (exactly = input idx)
// w = 4p+q;  stage1: hi=q>>1, j=q&1 -> k = 16p + 4*t4 + 2*hi + j
//            stage2: s=2p+(q>>1), j=q&1 -> k = 8s + 2*t4 + j
__global__ void convert_weights_kernel(const float* __restrict__ Wv,
                                       const float* __restrict__ Wo) {
    int idx = blockIdx.x * blockDim.x + threadIdx.x;   // over 98304
    if (idx >= WFRAG_WORDS) return;
    int q    = idx & 3;
    int lane = (idx >> 2) & 31;
    int p    = (idx >> 7) & 3;
    int nb   = (idx >> 9) & 7;
    int c    = idx >> 12;
    int gid = lane >> 2, t4 = lane & 3;
    int n = nb * 8 + gid;
    float v;
    if (c < NCH1) {
        int kk = p * 16 + 4 * t4 + 2 * (q >> 1) + (q & 1);
        v = Wv[(size_t)n * DIM + c * 64 + kk];                    // Wv [64][768]
    } else {
        int s  = 2 * p + (q >> 1);
        int kk = s * 8 + 2 * t4 + (q & 1);
        v = Wo[(size_t)((c - NCH1) * 64 + n) * HH + kk];          // Wo [768][64]
    }
    g_Wfrag[idx] = f2tf32(v);
}

__global__ __launch_bounds__(NTHREADS, 2)
void pooling_retriever_kernel(const float* __restrict__ x,
                              const float* __restrict__ bv,
                              const float* __restrict__ bo,
                              float* __restrict__ out) {
    const int tid  = threadIdx.x;
    const int warp = tid >> 5;
    const int lane = tid & 31;
    const int gid  = lane >> 2;
    const int t4   = lane & 3;
    const int m0   = blockIdx.x * TILE_M;
    const int wrow = warp * 16;

    const uint4* wf = (const uint4*)g_Wfrag;   // [(c*8+nb)*4+p]*32 + lane

    // this thread's two x rows (gid, gid+8), k-offset 4*t4
    const float* xr0 = x + (size_t)(m0 + wrow + gid) * DIM + 4 * t4;
    const float* xr1 = xr0 + 8 * DIM;

    // ---------------- Stage 1: T = x @ Wv.T  (acc in regs) ----------------
    float acc[8][4];
    #pragma unroll
    for (int nb = 0; nb < 8; nb++)
        #pragma unroll
        for (int i = 0; i < 4; i++) acc[nb][i] = 0.f;

    for (int k = 0; k < NCH1; k++) {
        // front-batch all 8 independent x loads for this chunk
        float4 v0[4], v1[4];
        #pragma unroll
        for (int p = 0; p < 4; p++) {
            v0[p] = *(const float4*)(xr0 + k * 64 + 16 * p);
            v1[p] = *(const float4*)(xr1 + k * 64 + 16 * p);
        }
        #pragma unroll
        for (int p = 0; p < 4; p++) {
            uint32_t ae[4], ao[4];
            ae[0] = f2tf32(v0[p].x); ae[1] = f2tf32(v1[p].x);
            ae[2] = f2tf32(v0[p].y); ae[3] = f2tf32(v1[p].y);
            ao[0] = f2tf32(v0[p].z); ao[1] = f2tf32(v1[p].z);
            ao[2] = f2tf32(v0[p].w); ao[3] = f2tf32(v1[p].w);
            #pragma unroll
            for (int nb = 0; nb < 8; nb++) {
                uint4 B = wf[((size_t)(k * 8 + nb) * 4 + p) * 32 + lane];
                mma8(acc[nb], ae, B.x, B.y);
                mma8(acc[nb], ao, B.z, B.w);
            }
        }
    }

    // ---- T + bv -> stage-2 A fragments entirely in registers (k-remap) ----
    uint32_t ta[8][4];
    #pragma unroll
    for (int s = 0; s < 8; s++) {
        int c = s * 8 + 2 * t4;
        float2 b = __ldg((const float2*)(bv + c));
        ta[s][0] = f2tf32(acc[s][0] + b.x);   // (row gid,   k = c)
        ta[s][1] = f2tf32(acc[s][2] + b.x);   // (row gid+8, k = c)
        ta[s][2] = f2tf32(acc[s][1] + b.y);   // (row gid,   k = c+1)
        ta[s][3] = f2tf32(acc[s][3] + b.y);   // (row gid+8, k = c+1)
    }

    // ---------------- Stage 2: out = T @ Wo.T + bo ----------------
    float* orow0 = out + (size_t)(m0 + wrow + gid) * DIM;
    for (int k = NCH1; k < NCH; k++) {
        const int nc = (k - NCH1) * 64;
        #pragma unroll
        for (int nb = 0; nb < 8; nb++)
            #pragma unroll
            for (int i = 0; i < 4; i++) acc[nb][i] = 0.f;

        #pragma unroll
        for (int p = 0; p < 4; p++) {
            #pragma unroll
            for (int nb = 0; nb < 8; nb++) {
                uint4 B = wf[((size_t)(k * 8 + nb) * 4 + p) * 32 + lane];
                mma8(acc[nb], ta[2 * p],     B.x, B.y);
                mma8(acc[nb], ta[2 * p + 1], B.z, B.w);
            }
        }
        #pragma unroll
        for (int nb = 0; nb < 8; nb++) {
            int c = nb * 8 + 2 * t4;
            float2 b = __ldg((const float2*)(bo + nc + c));
            float2 u0 = make_float2(acc[nb][0] + b.x, acc[nb][1] + b.y);
            float2 u1 = make_float2(acc[nb][2] + b.x, acc[nb][3] + b.y);
            *(float2*)(orow0 + nc + c)           = u0;
            *(float2*)(orow0 + 8 * DIM + nc + c) = u1;
        }
    }
}

extern "C" void kernel_launch(void* const* d_in, const int* in_sizes, int n_in,
                              void* d_out, int out_size) {
    // metadata order: x, q_state, Wq, bq, Wk, bk, Wv, bv, Wo, bo
    const float* x  = (const float*)d_in[0];
    const float* Wv = (const float*)d_in[6];
    const float* bv = (const float*)d_in[7];
    const float* Wo = (const float*)d_in[8];
    const float* bo = (const float*)d_in[9];
    float* out = (float*)d_out;

    const int n_rows = in_sizes[0] / DIM;      // 65536
    const int grid   = n_rows / TILE_M;        // 512

    convert_weights_kernel<<<384, 256>>>(Wv, Wo);
    pooling_retriever_kernel<<<grid, NTHREADS>>>(x, bv, bo, out);
}

// round 11
// speedup vs baseline: 1.3252x; 1.3252x over previous
#include <cuda_runtime.h>
#include <cstdint>

// out = (x @ Wv.T + bv) @ Wo.T + bo   (softmax over singleton axis == 1)
// R8: R5 skeleton (B via cp.async->smem LDS.128, x via direct permuted
// LDG.128, register T handoff) + m32 warp tiles (halve B LDS per MMA) +
// ring-3 W buffer with a single __syncthreads per chunk.

#define DIM      768
#define HH       64
#define TILE_M   128
#define NTHREADS 128                      // 4 warps, m32 rows each
#define WCH      (8 * 32 * 20)            // 5120 words per W chunk (frag order)
#define SMEM_BYTES (3 * WCH * 4)          // 61440: ring of 3 chunks
#define NCH1     12
#define NCH      24

__device__ uint32_t g_Wfrag[NCH * WCH];   // 480 KB, L2-resident

__device__ __forceinline__ uint32_t f2tf32(float f) {
    uint32_t r;
    asm("cvt.rna.tf32.f32 %0, %1;" : "=r"(r) : "f"(f));
    return r;
}

__device__ __forceinline__ void cp16(void* sdst, const void* gsrc) {
    uint32_t s = (uint32_t)__cvta_generic_to_shared(sdst);
    asm volatile("cp.async.ca.shared.global [%0], [%1], 16;\n" :: "r"(s), "l"(gsrc));
}

__device__ __forceinline__ void mma8(float d[4], const uint32_t a[4], uint32_t b0, uint32_t b1) {
    asm volatile(
        "mma.sync.aligned.m16n8k8.row.col.f32.tf32.tf32.f32 "
        "{%0,%1,%2,%3}, {%4,%5,%6,%7}, {%8,%9}, {%0,%1,%2,%3};\n"
        : "+f"(d[0]), "+f"(d[1]), "+f"(d[2]), "+f"(d[3])
        : "r"(a[0]), "r"(a[1]), "r"(a[2]), "r"(a[3]), "r"(b0), "r"(b1));
}

// Prologue: permute Wv/Wo into per-lane fragment order (identical to R5).
// word layout: [(c*8+nb)*32 + lane]*20 + w,  w in 0..15, lane stride 20 (80B).
// stage 1 (c<12):  p=w>>2, hi=(w>>1)&1, j=w&1 -> k = 16p + 4*t4 + 2*hi + j
// stage 2 (c>=12): s=2*(w>>2)+((w>>1)&1), j=w&1 -> k = 8s + 2*t4 + j
__global__ void convert_weights_kernel(const float* __restrict__ Wv,
                                       const float* __restrict__ Wo) {
    int idx = blockIdx.x * blockDim.x + threadIdx.x;   // 24*8*32*16 = 98304
    if (idx >= NCH * 8 * 32 * 16) return;
    int w  = idx & 15;
    int l  = (idx >> 4) & 31;
    int nb = (idx >> 9) & 7;
    int c  = idx >> 12;
    int gid = l >> 2, t4 = l & 3;
    int p  = w >> 2, hi = (w >> 1) & 1, j = w & 1;
    int n  = nb * 8 + gid;
    float v;
    if (c < NCH1) {
        int kk = p * 16 + 4 * t4 + 2 * hi + j;
        v = Wv[(size_t)n * DIM + c * 64 + kk];                   // Wv [64][768]
    } else {
        int s  = 2 * p + hi;
        int kk = s * 8 + 2 * t4 + j;
        v = Wo[(size_t)((c - NCH1) * 64 + n) * HH + kk];         // Wo [768][64]
    }
    g_Wfrag[((size_t)(c * 8 + nb) * 32 + l) * 20 + w] = f2tf32(v);
}

__global__ __launch_bounds__(NTHREADS, 2)
void pooling_retriever_kernel(const float* __restrict__ x,
                              const float* __restrict__ bv,
                              const float* __restrict__ bo,
                              float* __restrict__ out) {
    extern __shared__ uint32_t smem[];     // ring of 3 W chunks

    const int tid  = threadIdx.x;
    const int warp = tid >> 5;
    const int lane = tid & 31;
    const int gid  = lane >> 2;
    const int t4   = lane & 3;
    const int m0   = blockIdx.x * TILE_M;
    const int wrow = warp * 32;            // 32 rows per warp

    auto issue_w = [&](int k) {
        uint32_t* wb = smem + (k % 3) * WCH;
        const uint32_t* gsrc = g_Wfrag + (size_t)k * WCH;
        #pragma unroll
        for (int i = 0; i < 10; i++) {     // 5120 words = 1280 uint4, 128 thr
            int u = tid + i * NTHREADS;
            cp16(wb + u * 4, gsrc + u * 4);
        }
        asm volatile("cp.async.commit_group;\n");
    };

    issue_w(0);
    issue_w(1);

    // this thread's four x rows: wrow + {gid, gid+8, gid+16, gid+24}
    const float* xr0 = x + (size_t)(m0 + wrow + gid) * DIM + 4 * t4;

    // ---------------- Stage 1: T = x @ Wv.T  (acc in regs) ----------------
    float acc[2][8][4];
    #pragma unroll
    for (int mt = 0; mt < 2; mt++)
        #pragma unroll
        for (int nb = 0; nb < 8; nb++)
            #pragma unroll
            for (int i = 0; i < 4; i++) acc[mt][nb][i] = 0.f;

    for (int k = 0; k < NCH1; k++) {
        asm volatile("cp.async.wait_group 1;\n");   // chunk k landed (this thread)
        __syncthreads();                            // visible + buf (k+2)%3 free
        issue_w(k + 2);                             // k+2 <= 13 < NCH always

        // front-batch 16 independent x LDG.128
        float4 v0[2][4], v1[2][4];
        #pragma unroll
        for (int mt = 0; mt < 2; mt++) {
            const float* r0 = xr0 + (size_t)(mt * 16) * DIM + k * 64;
            #pragma unroll
            for (int p = 0; p < 4; p++) {
                v0[mt][p] = *(const float4*)(r0 + 16 * p);
                v1[mt][p] = *(const float4*)(r0 + 8 * DIM + 16 * p);
            }
        }
        const uint32_t* wb = smem + (k % 3) * WCH;
        #pragma unroll
        for (int p = 0; p < 4; p++) {
            uint32_t ae[2][4], ao[2][4];
            #pragma unroll
            for (int mt = 0; mt < 2; mt++) {
                ae[mt][0] = f2tf32(v0[mt][p].x); ae[mt][1] = f2tf32(v1[mt][p].x);
                ae[mt][2] = f2tf32(v0[mt][p].y); ae[mt][3] = f2tf32(v1[mt][p].y);
                ao[mt][0] = f2tf32(v0[mt][p].z); ao[mt][1] = f2tf32(v1[mt][p].z);
                ao[mt][2] = f2tf32(v0[mt][p].w); ao[mt][3] = f2tf32(v1[mt][p].w);
            }
            #pragma unroll
            for (int nb = 0; nb < 8; nb++) {
                uint4 B = *(const uint4*)(wb + (nb * 32 + lane) * 20 + p * 4);
                mma8(acc[0][nb], ae[0], B.x, B.y);
                mma8(acc[0][nb], ao[0], B.z, B.w);
                mma8(acc[1][nb], ae[1], B.x, B.y);
                mma8(acc[1][nb], ao[1], B.z, B.w);
            }
        }
    }

    // ---- T + bv -> stage-2 A fragments entirely in registers (k-remap) ----
    uint32_t ta[2][8][4];
    #pragma unroll
    for (int s = 0; s < 8; s++) {
        int c = s * 8 + 2 * t4;
        float2 b = __ldg((const float2*)(bv + c));
        #pragma unroll
        for (int mt = 0; mt < 2; mt++) {
            ta[mt][s][0] = f2tf32(acc[mt][s][0] + b.x);   // (row, k = c)
            ta[mt][s][1] = f2tf32(acc[mt][s][2] + b.x);   // (row+8, k = c)
            ta[mt][s][2] = f2tf32(acc[mt][s][1] + b.y);   // (row, k = c+1)
            ta[mt][s][3] = f2tf32(acc[mt][s][3] + b.y);   // (row+8, k = c+1)
        }
    }

    // ---------------- Stage 2: out = T @ Wo.T + bo ----------------
    float* orow0 = out + (size_t)(m0 + wrow + gid) * DIM;
    for (int k = NCH1; k < NCH; k++) {
        const int nc = (k - NCH1) * 64;
        if (k < NCH - 1) asm volatile("cp.async.wait_group 1;\n");
        else             asm volatile("cp.async.wait_group 0;\n");
        __syncthreads();
        if (k + 2 < NCH) issue_w(k + 2);

        const uint32_t* wb = smem + (k % 3) * WCH;
        #pragma unroll
        for (int mt = 0; mt < 2; mt++)
            #pragma unroll
            for (int nb = 0; nb < 8; nb++)
                #pragma unroll
                for (int i = 0; i < 4; i++) acc[mt][nb][i] = 0.f;

        #pragma unroll
        for (int p = 0; p < 4; p++) {
            #pragma unroll
            for (int nb = 0; nb < 8; nb++) {
                uint4 B = *(const uint4*)(wb + (nb * 32 + lane) * 20 + p * 4);
                mma8(acc[0][nb], ta[0][2 * p],     B.x, B.y);
                mma8(acc[0][nb], ta[0][2 * p + 1], B.z, B.w);
                mma8(acc[1][nb], ta[1][2 * p],     B.x, B.y);
                mma8(acc[1][nb], ta[1][2 * p + 1], B.z, B.w);
            }
        }
        #pragma unroll
        for (int nb = 0; nb < 8; nb++) {
            int c = nb * 8 + 2 * t4;
            float2 b = __ldg((const float2*)(bo + nc + c));
            #pragma unroll
            for (int mt = 0; mt < 2; mt++) {
                float* r0 = orow0 + (size_t)(mt * 16) * DIM + nc + c;
                *(float2*)(r0)           = make_float2(acc[mt][nb][0] + b.x,
                                                       acc[mt][nb][1] + b.y);
                *(float2*)(r0 + 8 * DIM) = make_float2(acc[mt][nb][2] + b.x,
                                                       acc[mt][nb][3] + b.y);
            }
        }
    }
}

extern "C" void kernel_launch(void* const* d_in, const int* in_sizes, int n_in,
                              void* d_out, int out_size) {
    // metadata order: x, q_state, Wq, bq, Wk, bk, Wv, bv, Wo, bo
    const float* x  = (const float*)d_in[0];
    const float* Wv = (const float*)d_in[6];
    const float* bv = (const float*)d_in[7];
    const float* Wo = (const float*)d_in[8];
    const float* bo = (const float*)d_in[9];
    float* out = (float*)d_out;

    const int n_rows = in_sizes[0] / DIM;      // 65536
    const int grid   = n_rows / TILE_M;        // 512

    convert_weights_kernel<<<384, 256>>>(Wv, Wo);

    cudaFuncSetAttribute(pooling_retriever_kernel,
                         cudaFuncAttributeMaxDynamicSharedMemorySize, SMEM_BYTES);
    pooling_retriever_kernel<<<grid, NTHREADS, SMEM_BYTES>>>(x, bv, bo, out);
}

// round 12
// speedup vs baseline: 1.3892x; 1.0483x over previous
#include <cuda_runtime.h>
#include <cstdint>

// out = (x @ Wv.T + bv) @ Wo.T + bo   (softmax over singleton axis == 1)
// R11: R5 base (256 thr, m16 warp tiles, B via cp.async smem LDS.128,
// register T handoff) + ring-3 W buffer with 1 sync/chunk (R8) +
// NEW: x software-pipelined one chunk ahead in registers, so the per-chunk
// GMEM latency (the plateau-maker) is covered by a full chunk of compute.

#define DIM      768
#define HH       64
#define TILE_M   128
#define NTHREADS 256                      // 8 warps, m16 rows each
#define WCH      (8 * 32 * 20)            // 5120 words per W chunk (frag order)
#define SMEM_BYTES (3 * WCH * 4)          // 61440: ring of 3 chunks
#define NCH1     12
#define NCH      24

__device__ uint32_t g_Wfrag[NCH * WCH];   // 480 KB, L2-resident

__device__ __forceinline__ uint32_t f2tf32(float f) {
    uint32_t r;
    asm("cvt.rna.tf32.f32 %0, %1;" : "=r"(r) : "f"(f));
    return r;
}

__device__ __forceinline__ void cp16(void* sdst, const void* gsrc) {
    uint32_t s = (uint32_t)__cvta_generic_to_shared(sdst);
    asm volatile("cp.async.ca.shared.global [%0], [%1], 16;\n" :: "r"(s), "l"(gsrc));
}

__device__ __forceinline__ void mma8(float d[4], const uint32_t a[4], uint32_t b0, uint32_t b1) {
    asm volatile(
        "mma.sync.aligned.m16n8k8.row.col.f32.tf32.tf32.f32 "
        "{%0,%1,%2,%3}, {%4,%5,%6,%7}, {%8,%9}, {%0,%1,%2,%3};\n"
        : "+f"(d[0]), "+f"(d[1]), "+f"(d[2]), "+f"(d[3])
        : "r"(a[0]), "r"(a[1]), "r"(a[2]), "r"(a[3]), "r"(b0), "r"(b1));
}

// Prologue: permute Wv/Wo into per-lane fragment order (identical to R5/R8).
// word layout: [(c*8+nb)*32 + lane]*20 + w,  w in 0..15, lane stride 20 (80B).
// stage 1 (c<12):  p=w>>2, hi=(w>>1)&1, j=w&1 -> k = 16p + 4*t4 + 2*hi + j
// stage 2 (c>=12): s=2*(w>>2)+((w>>1)&1), j=w&1 -> k = 8s + 2*t4 + j
__global__ void convert_weights_kernel(const float* __restrict__ Wv,
                                       const float* __restrict__ Wo) {
    int idx = blockIdx.x * blockDim.x + threadIdx.x;   // 24*8*32*16 = 98304
    if (idx >= NCH * 8 * 32 * 16) return;
    int w  = idx & 15;
    int l  = (idx >> 4) & 31;
    int nb = (idx >> 9) & 7;
    int c  = idx >> 12;
    int gid = l >> 2, t4 = l & 3;
    int p  = w >> 2, hi = (w >> 1) & 1, j = w & 1;
    int n  = nb * 8 + gid;
    float v;
    if (c < NCH1) {
        int kk = p * 16 + 4 * t4 + 2 * hi + j;
        v = Wv[(size_t)n * DIM + c * 64 + kk];                   // Wv [64][768]
    } else {
        int s  = 2 * p + hi;
        int kk = s * 8 + 2 * t4 + j;
        v = Wo[(size_t)((c - NCH1) * 64 + n) * HH + kk];         // Wo [768][64]
    }
    g_Wfrag[((size_t)(c * 8 + nb) * 32 + l) * 20 + w] = f2tf32(v);
}

__global__ __launch_bounds__(NTHREADS, 2)
void pooling_retriever_kernel(const float* __restrict__ x,
                              const float* __restrict__ bv,
                              const float* __restrict__ bo,
                              float* __restrict__ out) {
    extern __shared__ uint32_t smem[];     // ring of 3 W chunks

    const int tid  = threadIdx.x;
    const int warp = tid >> 5;
    const int lane = tid & 31;
    const int gid  = lane >> 2;
    const int t4   = lane & 3;
    const int m0   = blockIdx.x * TILE_M;
    const int wrow = warp * 16;

    auto issue_w = [&](int k) {
        uint32_t* wb = smem + (k % 3) * WCH;
        const uint32_t* gsrc = g_Wfrag + (size_t)k * WCH;
        #pragma unroll
        for (int i = 0; i < 5; i++) {      // 5120 words = 1280 uint4, 256 thr
            int u = tid + i * NTHREADS;
            cp16(wb + u * 4, gsrc + u * 4);
        }
        asm volatile("cp.async.commit_group;\n");
    };

    issue_w(0);
    issue_w(1);

    // this thread's two x rows (gid, gid+8), k-offset 4*t4
    const float* xr0 = x + (size_t)(m0 + wrow + gid) * DIM + 4 * t4;
    const float* xr1 = xr0 + 8 * DIM;

    // ---------------- Stage 1: T = x @ Wv.T  (acc in regs) ----------------
    float acc[8][4];
    #pragma unroll
    for (int nb = 0; nb < 8; nb++)
        #pragma unroll
        for (int i = 0; i < 4; i++) acc[nb][i] = 0.f;

    float4 vA0[4], vA1[4], vB0[4], vB1[4];   // ping-pong x register buffers

    // preload chunk 0 into A
    #pragma unroll
    for (int p = 0; p < 4; p++) {
        vA0[p] = *(const float4*)(xr0 + 16 * p);
        vA1[p] = *(const float4*)(xr1 + 16 * p);
    }

    // one pipelined step: prefetch chunk k+1 into (n0,n1), compute chunk k from (c0,c1)
    auto step1 = [&](int k, float4 c0[4], float4 c1[4], float4 n0[4], float4 n1[4]) {
        if (k + 1 < NCH1) {                    // prefetch next x chunk FIRST
            #pragma unroll
            for (int p = 0; p < 4; p++) {
                n0[p] = *(const float4*)(xr0 + (k + 1) * 64 + 16 * p);
                n1[p] = *(const float4*)(xr1 + (k + 1) * 64 + 16 * p);
            }
        }
        asm volatile("cp.async.wait_group 1;\n");   // W chunk k landed
        __syncthreads();                            // visible + buf (k+2)%3 free
        issue_w(k + 2);                             // k+2 <= 13 < NCH

        const uint32_t* wb = smem + (k % 3) * WCH;
        #pragma unroll
        for (int p = 0; p < 4; p++) {
            uint32_t ae[4], ao[4];
            ae[0] = f2tf32(c0[p].x); ae[1] = f2tf32(c1[p].x);
            ae[2] = f2tf32(c0[p].y); ae[3] = f2tf32(c1[p].y);
            ao[0] = f2tf32(c0[p].z); ao[1] = f2tf32(c1[p].z);
            ao[2] = f2tf32(c0[p].w); ao[3] = f2tf32(c1[p].w);
            #pragma unroll
            for (int nb = 0; nb < 8; nb++) {
                uint4 B = *(const uint4*)(wb + (nb * 32 + lane) * 20 + p * 4);
                mma8(acc[nb], ae, B.x, B.y);
                mma8(acc[nb], ao, B.z, B.w);
            }
        }
    };

    #pragma unroll
    for (int kk = 0; kk < NCH1; kk += 2) {
        step1(kk,     vA0, vA1, vB0, vB1);
        step1(kk + 1, vB0, vB1, vA0, vA1);
    }

    // ---- T + bv -> stage-2 A fragments entirely in registers (k-remap) ----
    uint32_t ta[8][4];
    #pragma unroll
    for (int s = 0; s < 8; s++) {
        int c = s * 8 + 2 * t4;
        float2 b = __ldg((const float2*)(bv + c));
        ta[s][0] = f2tf32(acc[s][0] + b.x);   // (row gid,   k = c)
        ta[s][1] = f2tf32(acc[s][2] + b.x);   // (row gid+8, k = c)
        ta[s][2] = f2tf32(acc[s][1] + b.y);   // (row gid,   k = c+1)
        ta[s][3] = f2tf32(acc[s][3] + b.y);   // (row gid+8, k = c+1)
    }

    // ---------------- Stage 2: out = T @ Wo.T + bo ----------------
    float* orow0 = out + (size_t)(m0 + wrow + gid) * DIM;
    for (int k = NCH1; k < NCH; k++) {
        const int nc = (k - NCH1) * 64;
        if (k < NCH - 1) asm volatile("cp.async.wait_group 1;\n");
        else             asm volatile("cp.async.wait_group 0;\n");
        __syncthreads();
        if (k + 2 < NCH) issue_w(k + 2);

        const uint32_t* wb = smem + (k % 3) * WCH;
        #pragma unroll
        for (int nb = 0; nb < 8; nb++)
            #pragma unroll
            for (int i = 0; i < 4; i++) acc[nb][i] = 0.f;

        #pragma unroll
        for (int p = 0; p < 4; p++) {
            #pragma unroll
            for (int nb = 0; nb < 8; nb++) {
                uint4 B = *(const uint4*)(wb + (nb * 32 + lane) * 20 + p * 4);
                mma8(acc[nb], ta[2 * p],     B.x, B.y);
                mma8(acc[nb], ta[2 * p + 1], B.z, B.w);
            }
        }
        #pragma unroll
        for (int nb = 0; nb < 8; nb++) {
            int c = nb * 8 + 2 * t4;
            float2 b = __ldg((const float2*)(bo + nc + c));
            float2 u0 = make_float2(acc[nb][0] + b.x, acc[nb][1] + b.y);
            float2 u1 = make_float2(acc[nb][2] + b.x, acc[nb][3] + b.y);
            *(float2*)(orow0 + nc + c)           = u0;
            *(float2*)(orow0 + 8 * DIM + nc + c) = u1;
        }
    }
}

extern "C" void kernel_launch(void* const* d_in, const int* in_sizes, int n_in,
                              void* d_out, int out_size) {
    // metadata order: x, q_state, Wq, bq, Wk, bk, Wv, bv, Wo, bo
    const float* x  = (const float*)d_in[0];
    const float* Wv = (const float*)d_in[6];
    const float* bv = (const float*)d_in[7];
    const float* Wo = (const float*)d_in[8];
    const float* bo = (const float*)d_in[9];
    float* out = (float*)d_out;

    const int n_rows = in_sizes[0] / DIM;      // 65536
    const int grid   = n_rows / TILE_M;        // 512

    convert_weights_kernel<<<384, 256>>>(Wv, Wo);

    cudaFuncSetAttribute(pooling_retriever_kernel,
                         cudaFuncAttributeMaxDynamicSharedMemorySize, SMEM_BYTES);
    pooling_retriever_kernel<<<grid, NTHREADS, SMEM_BYTES>>>(x, bv, bo, out);
}

// round 16
// speedup vs baseline: 1.7543x; 1.2628x over previous
#include <cuda_runtime.h>
#include <cuda_fp16.h>
#include <cstdint>

// out = (x @ Wv.T + bv) @ Wo.T + bo   (softmax over singleton axis == 1)
// R14: fp16 m16n8k16 MMA (11-bit mantissa == tf32, half the instructions and
// half the B bytes) + 3 CTAs/SM (24 warps). R11/R5 skeleton otherwise:
// x via direct permuted LDG.128, W via cp.async ring-3 smem (frag-order
// LDS.64), T handoff entirely in registers, 1 syncthreads per chunk.

#define DIM      768
#define HH       64
#define TILE_M   128
#define NTHREADS 256                   // 8 warps, m16 rows each
#define NCH1     12
#define NCH      24
#define WCHB     8192                  // W chunk: 8 nb x 4 p x 32 lanes x 8B
#define SMEM_BYTES (3 * WCHB)          // 24KB ring of 3 chunks

__device__ uint2 g_Wh[NCH * 8 * 4 * 32];   // 192 KB fp16 fragment images

__device__ __forceinline__ uint32_t f2h2(float lo, float hi) {
    __half2 h = __floats2half2_rn(lo, hi);   // lo -> .x (low 16), hi -> .y
    return *(uint32_t*)&h;
}

__device__ __forceinline__ void cp16(void* sdst, const void* gsrc) {
    uint32_t s = (uint32_t)__cvta_generic_to_shared(sdst);
    asm volatile("cp.async.ca.shared.global [%0], [%1], 16;\n" :: "r"(s), "l"(gsrc));
}

__device__ __forceinline__ void mma16(float d[4], const uint32_t a[4],
                                      uint32_t b0, uint32_t b1) {
    asm volatile(
        "mma.sync.aligned.m16n8k16.row.col.f32.f16.f16.f32 "
        "{%0,%1,%2,%3}, {%4,%5,%6,%7}, {%8,%9}, {%0,%1,%2,%3};\n"
        : "+f"(d[0]), "+f"(d[1]), "+f"(d[2]), "+f"(d[3])
        : "r"(a[0]), "r"(a[1]), "r"(a[2]), "r"(a[3]), "r"(b0), "r"(b1));
}

// Prologue: build fp16 B-fragment images with the SAME k-mapping the main
// kernel's A side uses.  elem idx = ((c*8+nb)*4+p)*32+lane, uint2 = (b0,b1).
// stage 1 (c<12): frag pair (2t4,2t4+1)   <-> k = c*64 + 16p + 4t4 + {0,1}
//                 frag pair (2t4+8,2t4+9) <-> k = c*64 + 16p + 4t4 + {2,3}
//                 (matches a float4 x-load at offset 16p + 4t4)
// stage 2 (c>=12): identity k mapping within the 16-window:
//                 b0 = {Wo[n][16p+2t4], +1},  b1 = {Wo[n][16p+8+2t4], +1}
__global__ void convert_weights_kernel(const float* __restrict__ Wv,
                                       const float* __restrict__ Wo) {
    int idx = blockIdx.x * blockDim.x + threadIdx.x;   // 24*8*4*32 = 24576
    if (idx >= NCH * 8 * 4 * 32) return;
    int lane = idx & 31;
    int p    = (idx >> 5) & 3;
    int nb   = (idx >> 7) & 7;
    int c    = idx >> 10;
    int gid = lane >> 2, t4 = lane & 3;
    float w0, w1, w2, w3;
    if (c < NCH1) {
        int n = nb * 8 + gid;
        const float* wr = Wv + (size_t)n * DIM + c * 64 + p * 16 + 4 * t4;
        w0 = wr[0]; w1 = wr[1]; w2 = wr[2]; w3 = wr[3];
    } else {
        int n = (c - NCH1) * 64 + nb * 8 + gid;        // Wo row = out column
        const float* wr = Wo + (size_t)n * HH + p * 16;
        w0 = wr[2 * t4];     w1 = wr[2 * t4 + 1];
        w2 = wr[8 + 2 * t4]; w3 = wr[8 + 2 * t4 + 1];
    }
    uint2 u;
    u.x = f2h2(w0, w1);
    u.y = f2h2(w2, w3);
    g_Wh[idx] = u;
}

__global__ __launch_bounds__(NTHREADS, 3)
void pooling_retriever_kernel(const float* __restrict__ x,
                              const float* __restrict__ bv,
                              const float* __restrict__ bo,
                              float* __restrict__ out) {
    extern __shared__ char smem[];     // ring of 3 W chunks (8KB each)

    const int tid  = threadIdx.x;
    const int warp = tid >> 5;
    const int lane = tid & 31;
    const int gid  = lane >> 2;
    const int t4   = lane & 3;
    const int m0   = blockIdx.x * TILE_M;
    const int wrow = warp * 16;

    auto issue_w = [&](int k) {
        char* wb = smem + (k % 3) * WCHB;
        const char* gsrc = (const char*)(g_Wh + (size_t)k * 8 * 4 * 32);
        #pragma unroll
        for (int i = 0; i < 2; i++) {  // 8192B = 512 uint4, 256 threads
            int u = tid + i * NTHREADS;
            cp16(wb + u * 16, gsrc + u * 16);
        }
        asm volatile("cp.async.commit_group;\n");
    };

    issue_w(0);
    issue_w(1);

    // this thread's two x rows (gid, gid+8), k-offset 4*t4
    const float* xr0 = x + (size_t)(m0 + wrow + gid) * DIM + 4 * t4;
    const float* xr1 = xr0 + 8 * DIM;

    // ---------------- Stage 1: T = x @ Wv.T  (acc in regs) ----------------
    float acc[8][4];
    #pragma unroll
    for (int nb = 0; nb < 8; nb++)
        #pragma unroll
        for (int i = 0; i < 4; i++) acc[nb][i] = 0.f;

    for (int k = 0; k < NCH1; k++) {
        asm volatile("cp.async.wait_group 1;\n");   // W chunk k landed
        __syncthreads();                            // visible + buf (k+2)%3 free
        issue_w(k + 2);                             // k+2 <= 13 < NCH

        // front-batch 8 independent x LDG.128 (steps p = 0..3, two rows)
        float4 v0[4], v1[4];
        #pragma unroll
        for (int p = 0; p < 4; p++) {
            v0[p] = *(const float4*)(xr0 + k * 64 + 16 * p);
            v1[p] = *(const float4*)(xr1 + k * 64 + 16 * p);
        }
        const uint2* wb = (const uint2*)(smem + (k % 3) * WCHB);
        #pragma unroll
        for (int p = 0; p < 4; p++) {
            uint32_t a[4];
            a[0] = f2h2(v0[p].x, v0[p].y);   // row gid,   k pair 4t4+{0,1}
            a[1] = f2h2(v1[p].x, v1[p].y);   // row gid+8
            a[2] = f2h2(v0[p].z, v0[p].w);   // row gid,   k pair 4t4+{2,3}
            a[3] = f2h2(v1[p].z, v1[p].w);   // row gid+8
            #pragma unroll
            for (int nb = 0; nb < 8; nb++) {
                uint2 B = wb[(nb * 4 + p) * 32 + lane];
                mma16(acc[nb], a, B.x, B.y);
            }
        }
    }

    // ---- T + bv -> stage-2 A fragments entirely in registers ----
    // acc[nb][0,1] = T[row gid][col nb*8+2t4, +1]; [2,3] = row gid+8.
    // stage-2 step p needs cols 16p..16p+16: nb = 2p (pairs 2t4) and
    // nb = 2p+1 (pairs 8+2t4) -> natural half2 pairs, no shuffles.
    uint32_t ta[4][4];
    #pragma unroll
    for (int p = 0; p < 4; p++) {
        float2 bA = __ldg((const float2*)(bv + 16 * p + 2 * t4));
        float2 bB = __ldg((const float2*)(bv + 16 * p + 8 + 2 * t4));
        ta[p][0] = f2h2(acc[2 * p][0] + bA.x, acc[2 * p][1] + bA.y);
        ta[p][1] = f2h2(acc[2 * p][2] + bA.x, acc[2 * p][3] + bA.y);
        ta[p][2] = f2h2(acc[2 * p + 1][0] + bB.x, acc[2 * p + 1][1] + bB.y);
        ta[p][3] = f2h2(acc[2 * p + 1][2] + bB.x, acc[2 * p + 1][3] + bB.y);
    }

    // ---------------- Stage 2: out = T @ Wo.T + bo ----------------
    float* orow0 = out + (size_t)(m0 + wrow + gid) * DIM;
    for (int k = NCH1; k < NCH; k++) {
        const int nc = (k - NCH1) * 64;
        if (k < NCH - 1) asm volatile("cp.async.wait_group 1;\n");
        else             asm volatile("cp.async.wait_group 0;\n");
        __syncthreads();
        if (k + 2 < NCH) issue_w(k + 2);

        const uint2* wb = (const uint2*)(smem + (k % 3) * WCHB);
        #pragma unroll
        for (int nb = 0; nb < 8; nb++)
            #pragma unroll
            for (int i = 0; i < 4; i++) acc[nb][i] = 0.f;

        #pragma unroll
        for (int p = 0; p < 4; p++) {
            #pragma unroll
            for (int nb = 0; nb < 8; nb++) {
                uint2 B = wb[(nb * 4 + p) * 32 + lane];
                mma16(acc[nb], ta[p], B.x, B.y);
            }
        }
        #pragma unroll
        for (int nb = 0; nb < 8; nb++) {
            int c = nb * 8 + 2 * t4;
            float2 b = __ldg((const float2*)(bo + nc + c));
            float2 u0 = make_float2(acc[nb][0] + b.x, acc[nb][1] + b.y);
            float2 u1 = make_float2(acc[nb][2] + b.x, acc[nb][3] + b.y);
            *(float2*)(orow0 + nc + c)           = u0;
            *(float2*)(orow0 + 8 * DIM + nc + c) = u1;
        }
    }
}

extern "C" void kernel_launch(void* const* d_in, const int* in_sizes, int n_in,
                              void* d_out, int out_size) {
    // metadata order: x, q_state, Wq, bq, Wk, bk, Wv, bv, Wo, bo
    const float* x  = (const float*)d_in[0];
    const float* Wv = (const float*)d_in[6];
    const float* bv = (const float*)d_in[7];
    const float* Wo = (const float*)d_in[8];
    const float* bo = (const float*)d_in[9];
    float* out = (float*)d_out;

    const int n_rows = in_sizes[0] / DIM;      // 65536
    const int grid   = n_rows / TILE_M;        // 512

    convert_weights_kernel<<<96, 256>>>(Wv, Wo);

    pooling_retriever_kernel<<<grid, NTHREADS, SMEM_BYTES>>>(x, bv, bo, out);
}